// round 1
// baseline (speedup 1.0000x reference)
#include <cuda_runtime.h>
#include <cuda_bf16.h>

#define IN_F   128
#define KGAUSS 4
#define OUT_F  32
#define KO     128   // KGAUSS * OUT_F

// node_feat scratch: [N][K*OUT_F] fp32, N <= 100096 (rounded up to tile)
__device__ float g_nf[100096 * 128];

// ---------------------------------------------------------------------------
// GEMM: C[n][o] = sum_j A[n][j] * W[o][j]     A:[N,128]  W:[128,128]  C:[N,128]
// 128-row tiles, full W^T in smem (padded), 8x8 register tile per thread.
// ---------------------------------------------------------------------------
extern "C" __global__ void __launch_bounds__(256, 2)
gmm_gemm_kernel(const float* __restrict__ A, const float* __restrict__ W,
                float* __restrict__ C, int N)
{
    extern __shared__ float smem[];
    float* Wt = smem;                 // [128][129]  Wt[j*129 + o] = W[o][j]
    float* As = smem + 128 * 129;     // [8][128]    As[kk*128 + row]

    const int tid = threadIdx.x;
    const int tx  = tid & 15;         // col group
    const int ty  = tid >> 4;         // row group
    const int rowBase = blockIdx.x * 128;

    // Load W transposed into smem. Read coalesced (o-major), store with +1 pad
    // so the strided store is conflict-free.
    for (int idx = tid; idx < KO * IN_F; idx += 256) {
        int o = idx >> 7;             // 0..127
        int j = idx & 127;            // 0..127
        Wt[j * 129 + o] = W[idx];
    }

    float acc[8][8];
#pragma unroll
    for (int r = 0; r < 8; r++)
#pragma unroll
        for (int c = 0; c < 8; c++) acc[r][c] = 0.0f;

    for (int j0 = 0; j0 < IN_F; j0 += 8) {
        __syncthreads();  // first iter: also fences Wt load
        {
            // 2 threads per row: each loads a float4 (8 j's per row total)
            int row = tid >> 1;
            int kkb = (tid & 1) * 4;
            int gr  = rowBase + row;
            float4 v = make_float4(0.f, 0.f, 0.f, 0.f);
            if (gr < N)
                v = *(const float4*)&A[(size_t)gr * IN_F + j0 + kkb];
            As[(kkb + 0) * 128 + row] = v.x;
            As[(kkb + 1) * 128 + row] = v.y;
            As[(kkb + 2) * 128 + row] = v.z;
            As[(kkb + 3) * 128 + row] = v.w;
        }
        __syncthreads();

#pragma unroll
        for (int kk = 0; kk < 8; kk++) {
            float a[8], b[8];
#pragma unroll
            for (int r = 0; r < 8; r++) a[r] = As[kk * 128 + ty + 16 * r];
#pragma unroll
            for (int c = 0; c < 8; c++) b[c] = Wt[(j0 + kk) * 129 + tx + 16 * c];
#pragma unroll
            for (int r = 0; r < 8; r++)
#pragma unroll
                for (int c = 0; c < 8; c++) acc[r][c] += a[r] * b[c];
        }
    }

#pragma unroll
    for (int r = 0; r < 8; r++) {
        int gr = rowBase + ty + 16 * r;
        if (gr < N) {
#pragma unroll
            for (int c = 0; c < 8; c++)
                C[(size_t)gr * KO + tx + 16 * c] = acc[r][c];
        }
    }
}

// ---------------------------------------------------------------------------
// Edge phase: one warp per dst node.
//   lane -> (k = lane>>3, f4 = lane&7): one float4 of NF[src][k][f4*4..+3]
//   per edge, one LDG.128 per lane covers the whole [K,OUT] slice per warp.
//   Cross-k reduction via shfl_xor(8), shfl_xor(16) at node end.
// ---------------------------------------------------------------------------
extern "C" __global__ void __launch_bounds__(256)
gmm_edge_kernel(const int* __restrict__ rowptr, const int* __restrict__ colind,
                const int* __restrict__ permute, const float* __restrict__ pseudo,
                const float* __restrict__ mu, const float* __restrict__ inv_sigma,
                const float* __restrict__ bias, const float* __restrict__ NF,
                float* __restrict__ out, int N)
{
    const unsigned FULL = 0xffffffffu;
    const int lane  = threadIdx.x & 31;
    const int gwarp = (blockIdx.x * blockDim.x + threadIdx.x) >> 5;
    const int nwarp = (gridDim.x * blockDim.x) >> 5;

    const int k  = lane >> 3;   // gaussian kernel index 0..3
    const int f4 = lane & 7;    // float4 index within OUT_F

    const float mu0 = mu[2 * k],        mu1 = mu[2 * k + 1];
    const float is0 = inv_sigma[2 * k], is1 = inv_sigma[2 * k + 1];
    // bias float4 for writer lanes
    float4 bv = make_float4(0.f, 0.f, 0.f, 0.f);
    if (lane < 8) bv = *(const float4*)&bias[f4 * 4];

    for (int i = gwarp; i < N; i += nwarp) {
        const int e0 = rowptr[i];
        const int e1 = rowptr[i + 1];

        float4 acc = make_float4(0.f, 0.f, 0.f, 0.f);

        for (int base = e0; base < e1; base += 32) {
            const int cnt = min(32, e1 - base);
            int   src_l = 0;
            float p0_l = 0.f, p1_l = 0.f;
            if (lane < cnt) {
                src_l = colind[base + lane];
                int pi = permute[base + lane];
                p0_l = pseudo[2 * pi];
                p1_l = pseudo[2 * pi + 1];
            }
            for (int e = 0; e < cnt; e++) {
                const int   src = __shfl_sync(FULL, src_l, e);
                const float p0  = __shfl_sync(FULL, p0_l, e);
                const float p1  = __shfl_sync(FULL, p1_l, e);
                const float d0  = (p0 - mu0) * is0;
                const float d1  = (p1 - mu1) * is1;
                const float w   = __expf(-0.5f * (d0 * d0 + d1 * d1));
                const float4 v  = *(const float4*)&NF[(size_t)src * KO + k * OUT_F + f4 * 4];
                acc.x += w * v.x;
                acc.y += w * v.y;
                acc.z += w * v.z;
                acc.w += w * v.w;
            }
        }

        // reduce across the 4 kernel groups (lanes differ in bits 3,4)
        acc.x += __shfl_xor_sync(FULL, acc.x, 8);
        acc.y += __shfl_xor_sync(FULL, acc.y, 8);
        acc.z += __shfl_xor_sync(FULL, acc.z, 8);
        acc.w += __shfl_xor_sync(FULL, acc.w, 8);
        acc.x += __shfl_xor_sync(FULL, acc.x, 16);
        acc.y += __shfl_xor_sync(FULL, acc.y, 16);
        acc.z += __shfl_xor_sync(FULL, acc.z, 16);
        acc.w += __shfl_xor_sync(FULL, acc.w, 16);

        if (lane < 8) {
            float4 o;
            o.x = acc.x + bv.x;
            o.y = acc.y + bv.y;
            o.z = acc.z + bv.z;
            o.w = acc.w + bv.w;
            *(float4*)&out[(size_t)i * OUT_F + f4 * 4] = o;
        }
    }
}

// ---------------------------------------------------------------------------
// Inputs (metadata order):
//  0 rowptr[N+1] i32, 1 colind[E] i32, 2 colptr i32, 3 rowind i32,
//  4 permute[E] i32, 5 feat[N*128] f32, 6 pseudo[E*2] f32,
//  7 fc_w[128*128] f32, 8 mu[4*2] f32, 9 inv_sigma[4*2] f32, 10 bias[32] f32
// ---------------------------------------------------------------------------
extern "C" void kernel_launch(void* const* d_in, const int* in_sizes, int n_in,
                              void* d_out, int out_size)
{
    const int*   rowptr    = (const int*)  d_in[0];
    const int*   colind    = (const int*)  d_in[1];
    const int*   permute   = (const int*)  d_in[4];
    const float* feat      = (const float*)d_in[5];
    const float* pseudo    = (const float*)d_in[6];
    const float* fc_w      = (const float*)d_in[7];
    const float* mu        = (const float*)d_in[8];
    const float* inv_sigma = (const float*)d_in[9];
    const float* bias      = (const float*)d_in[10];

    const int N = in_sizes[5] / IN_F;

    float* nf;
    cudaGetSymbolAddress((void**)&nf, g_nf);

    // GEMM: node_feat = feat @ fc_w.T
    const int smem_bytes = (128 * 129 + 8 * 128) * (int)sizeof(float);
    cudaFuncSetAttribute(gmm_gemm_kernel,
                         cudaFuncAttributeMaxDynamicSharedMemorySize, smem_bytes);
    const int gemm_blocks = (N + 127) / 128;
    gmm_gemm_kernel<<<gemm_blocks, 256, smem_bytes>>>(feat, fc_w, nf, N);

    // Edge phase: one warp per node
    const int warps_needed = N;
    const int edge_blocks  = (warps_needed * 32 + 255) / 256;
    gmm_edge_kernel<<<edge_blocks, 256>>>(rowptr, colind, permute, pseudo,
                                          mu, inv_sigma, bias, nf,
                                          (float*)d_out, N);
}

// round 2
// speedup vs baseline: 1.0174x; 1.0174x over previous
#include <cuda_runtime.h>
#include <cuda_bf16.h>

#define IN_F   128
#define KGAUSS 4
#define OUT_F  32
#define KO     128   // KGAUSS * OUT_F

// node_feat scratch: [N][K*OUT_F] fp32
__device__ float g_nf[100096 * 128];

// ---------------------------------------------------------------------------
// Packed fp32x2 FMA helpers (sm_103a FFMA2 — only reachable via PTX)
// ---------------------------------------------------------------------------
__device__ __forceinline__ void ffma2(unsigned long long& d,
                                      unsigned long long a,
                                      unsigned long long b) {
    asm("fma.rn.f32x2 %0, %1, %2, %0;" : "+l"(d) : "l"(a), "l"(b));
}
__device__ __forceinline__ unsigned long long dup_f32(float x) {
    unsigned long long r;
    asm("mov.b64 %0, {%1, %1};" : "=l"(r) : "f"(x));
    return r;
}
__device__ __forceinline__ float2 unpack_f32x2(unsigned long long v) {
    float lo, hi;
    asm("mov.b64 {%0, %1}, %2;" : "=f"(lo), "=f"(hi) : "l"(v));
    return make_float2(lo, hi);
}

// ---------------------------------------------------------------------------
// GEMM: C[n][o] = sum_j A[n][j] * W[o][j]   A:[N,128] W:[128,128] C:[N,128]
// 128-row tiles, W^T in smem (stride 130 -> 8B-aligned float2 reads),
// 8 rows x 4 column-PAIRS per thread, FFMA2 inner product.
// ---------------------------------------------------------------------------
extern "C" __global__ void __launch_bounds__(256, 2)
gmm_gemm_kernel(const float* __restrict__ A, const float* __restrict__ W,
                float* __restrict__ C, int N)
{
    extern __shared__ float smem[];
    float* Wt = smem;                 // [128][130]  Wt[j*130 + o] = W[o][j]
    float* As = smem + 128 * 130;     // [8][128]    As[kk*128 + row]

    const int tid = threadIdx.x;
    const int tx  = tid & 15;         // column-pair group: pairs at 2*tx + 32*c
    const int ty  = tid >> 4;         // row group
    const int rowBase = blockIdx.x * 128;

    for (int idx = tid; idx < KO * IN_F; idx += 256) {
        int o = idx >> 7;
        int j = idx & 127;
        Wt[j * 130 + o] = W[idx];
    }

    unsigned long long acc[8][4];
#pragma unroll
    for (int r = 0; r < 8; r++)
#pragma unroll
        for (int c = 0; c < 4; c++) acc[r][c] = 0ULL;

    for (int j0 = 0; j0 < IN_F; j0 += 8) {
        __syncthreads();  // first iter also fences Wt
        {
            int row = tid >> 1;
            int kkb = (tid & 1) * 4;
            int gr  = rowBase + row;
            float4 v = make_float4(0.f, 0.f, 0.f, 0.f);
            if (gr < N)
                v = *(const float4*)&A[(size_t)gr * IN_F + j0 + kkb];
            As[(kkb + 0) * 128 + row] = v.x;
            As[(kkb + 1) * 128 + row] = v.y;
            As[(kkb + 2) * 128 + row] = v.z;
            As[(kkb + 3) * 128 + row] = v.w;
        }
        __syncthreads();

#pragma unroll
        for (int kk = 0; kk < 8; kk++) {
            const unsigned long long* Wrow =
                (const unsigned long long*)&Wt[(j0 + kk) * 130];
            unsigned long long b[4];
#pragma unroll
            for (int c = 0; c < 4; c++) b[c] = Wrow[tx + 16 * c];
#pragma unroll
            for (int r = 0; r < 8; r++) {
                unsigned long long a2 = dup_f32(As[kk * 128 + ty + 16 * r]);
#pragma unroll
                for (int c = 0; c < 4; c++) ffma2(acc[r][c], a2, b[c]);
            }
        }
    }

#pragma unroll
    for (int r = 0; r < 8; r++) {
        int gr = rowBase + ty + 16 * r;
        if (gr < N) {
#pragma unroll
            for (int c = 0; c < 4; c++) {
                float2 v = unpack_f32x2(acc[r][c]);
                *(float2*)&C[(size_t)gr * KO + 2 * tx + 32 * c] = v;
            }
        }
    }
}

// ---------------------------------------------------------------------------
// Edge phase: one warp per dst node.
// Stage 1 (cooperative): lanes 0-15 fetch edge metadata; each lane computes
//   2 of the 64 (edge,kernel) gaussian weights -> smem (2 exps/lane/node).
// Stage 2: unrolled 16-edge gather: LDS src + LDS w + LDG.128 + 4 FFMA.
//   No shuffles in the hot loop.
// ---------------------------------------------------------------------------
extern "C" __global__ void __launch_bounds__(256, 3)
gmm_edge_kernel(const int* __restrict__ rowptr, const int* __restrict__ colind,
                const int* __restrict__ permute, const float* __restrict__ pseudo,
                const float* __restrict__ mu, const float* __restrict__ inv_sigma,
                const float* __restrict__ bias, const float* __restrict__ NF,
                float* __restrict__ out, int N)
{
    __shared__ int    s_src[8][16];
    __shared__ float2 s_p[8][16];
    __shared__ float  s_w[8][64];    // [e*4 + k]

    const unsigned FULL = 0xffffffffu;
    const int lane  = threadIdx.x & 31;
    const int wrp   = threadIdx.x >> 5;
    const int gwarp = (blockIdx.x * blockDim.x + threadIdx.x) >> 5;
    const int nwarp = (gridDim.x * blockDim.x) >> 5;

    const int k  = lane >> 3;   // gaussian kernel index 0..3 (main loop)
    const int f4 = lane & 7;    // float4 index within OUT_F

    // params for the 2 kernels this lane evaluates in stage 1
    const int kh = lane >> 4;               // 0 or 1 -> kernels {2kh, 2kh+1}
    const float muA0 = mu[4 * kh + 0], muA1 = mu[4 * kh + 1];
    const float muB0 = mu[4 * kh + 2], muB1 = mu[4 * kh + 3];
    const float isA0 = inv_sigma[4 * kh + 0], isA1 = inv_sigma[4 * kh + 1];
    const float isB0 = inv_sigma[4 * kh + 2], isB1 = inv_sigma[4 * kh + 3];

    float4 bv = make_float4(0.f, 0.f, 0.f, 0.f);
    if (lane < 8) bv = *(const float4*)&bias[f4 * 4];

    for (int i = gwarp; i < N; i += nwarp) {
        const int e0 = rowptr[i];
        const int e1 = rowptr[i + 1];

        float4 acc = make_float4(0.f, 0.f, 0.f, 0.f);

        for (int base = e0; base < e1; base += 16) {
            const int cnt = min(16, e1 - base);

            // stage 1a: fetch metadata (lanes 0..15)
            if (lane < cnt) {
                s_src[wrp][lane] = colind[base + lane];
                int pi = permute[base + lane];
                s_p[wrp][lane] = ((const float2*)pseudo)[pi];
            }
            __syncwarp(FULL);

            // stage 1b: gaussian weights, 2 per lane
            {
                int e = lane & 15;
                if (e < cnt) {
                    float2 p = s_p[wrp][e];
                    float d0 = (p.x - muA0) * isA0;
                    float d1 = (p.y - muA1) * isA1;
                    s_w[wrp][e * 4 + 2 * kh] =
                        __expf(-0.5f * (d0 * d0 + d1 * d1));
                    d0 = (p.x - muB0) * isB0;
                    d1 = (p.y - muB1) * isB1;
                    s_w[wrp][e * 4 + 2 * kh + 1] =
                        __expf(-0.5f * (d0 * d0 + d1 * d1));
                }
            }
            __syncwarp(FULL);

            // stage 2: gather + weighted accumulate
            if (cnt == 16) {
#pragma unroll
                for (int e = 0; e < 16; e++) {
                    int   src = s_src[wrp][e];
                    float w   = s_w[wrp][e * 4 + k];
                    float4 v  = *(const float4*)
                        &NF[(size_t)src * KO + k * OUT_F + f4 * 4];
                    acc.x += w * v.x;
                    acc.y += w * v.y;
                    acc.z += w * v.z;
                    acc.w += w * v.w;
                }
            } else {
                for (int e = 0; e < cnt; e++) {
                    int   src = s_src[wrp][e];
                    float w   = s_w[wrp][e * 4 + k];
                    float4 v  = *(const float4*)
                        &NF[(size_t)src * KO + k * OUT_F + f4 * 4];
                    acc.x += w * v.x;
                    acc.y += w * v.y;
                    acc.z += w * v.z;
                    acc.w += w * v.w;
                }
            }
            __syncwarp(FULL);
        }

        // reduce across the 4 kernel groups (lane bits 3,4)
        acc.x += __shfl_xor_sync(FULL, acc.x, 8);
        acc.y += __shfl_xor_sync(FULL, acc.y, 8);
        acc.z += __shfl_xor_sync(FULL, acc.z, 8);
        acc.w += __shfl_xor_sync(FULL, acc.w, 8);
        acc.x += __shfl_xor_sync(FULL, acc.x, 16);
        acc.y += __shfl_xor_sync(FULL, acc.y, 16);
        acc.z += __shfl_xor_sync(FULL, acc.z, 16);
        acc.w += __shfl_xor_sync(FULL, acc.w, 16);

        if (lane < 8) {
            float4 o;
            o.x = acc.x + bv.x;
            o.y = acc.y + bv.y;
            o.z = acc.z + bv.z;
            o.w = acc.w + bv.w;
            *(float4*)&out[(size_t)i * OUT_F + f4 * 4] = o;
        }
    }
}

// ---------------------------------------------------------------------------
// Inputs (metadata order):
//  0 rowptr[N+1] i32, 1 colind[E] i32, 2 colptr i32, 3 rowind i32,
//  4 permute[E] i32, 5 feat[N*128] f32, 6 pseudo[E*2] f32,
//  7 fc_w[128*128] f32, 8 mu[4*2] f32, 9 inv_sigma[4*2] f32, 10 bias[32] f32
// ---------------------------------------------------------------------------
extern "C" void kernel_launch(void* const* d_in, const int* in_sizes, int n_in,
                              void* d_out, int out_size)
{
    const int*   rowptr    = (const int*)  d_in[0];
    const int*   colind    = (const int*)  d_in[1];
    const int*   permute   = (const int*)  d_in[4];
    const float* feat      = (const float*)d_in[5];
    const float* pseudo    = (const float*)d_in[6];
    const float* fc_w      = (const float*)d_in[7];
    const float* mu        = (const float*)d_in[8];
    const float* inv_sigma = (const float*)d_in[9];
    const float* bias      = (const float*)d_in[10];

    const int N = in_sizes[5] / IN_F;

    float* nf;
    cudaGetSymbolAddress((void**)&nf, g_nf);

    const int smem_bytes = (128 * 130 + 8 * 128) * (int)sizeof(float);
    cudaFuncSetAttribute(gmm_gemm_kernel,
                         cudaFuncAttributeMaxDynamicSharedMemorySize, smem_bytes);
    const int gemm_blocks = (N + 127) / 128;
    gmm_gemm_kernel<<<gemm_blocks, 256, smem_bytes>>>(feat, fc_w, nf, N);

    const int edge_blocks = (N * 32 + 255) / 256;
    gmm_edge_kernel<<<edge_blocks, 256>>>(rowptr, colind, permute, pseudo,
                                          mu, inv_sigma, bias, nf,
                                          (float*)d_out, N);
}

// round 4
// speedup vs baseline: 1.1707x; 1.1508x over previous
#include <cuda_runtime.h>
#include <cuda_bf16.h>
#include <cuda_fp16.h>
#include <cstdint>

#define IN_F   128
#define KGAUSS 4
#define OUT_F  32
#define KO     128   // KGAUSS * OUT_F

// node_feat scratch: [N][K*OUT_F] fp16
__device__ __half g_nf[100096 * 128];

// ---------------------------------------------------------------------------
// helpers
// ---------------------------------------------------------------------------
__device__ __forceinline__ uint32_t smem_u32(const void* p) {
    uint32_t a;
    asm("{ .reg .u64 t; cvta.to.shared.u64 t, %1; cvt.u32.u64 %0, t; }"
        : "=r"(a) : "l"(p));
    return a;
}
__device__ __forceinline__ unsigned pack_bf2(float a, float b) {
    __nv_bfloat162 h = __floats2bfloat162_rn(a, b);
    return *reinterpret_cast<unsigned*>(&h);
}
__device__ __forceinline__ void ldsm4(uint32_t r[4], uint32_t addr) {
    asm volatile(
        "ldmatrix.sync.aligned.m8n8.x4.shared.b16 {%0,%1,%2,%3}, [%4];"
        : "=r"(r[0]), "=r"(r[1]), "=r"(r[2]), "=r"(r[3]) : "r"(addr));
}
__device__ __forceinline__ void mma_bf16(float c[4], const uint32_t a[4],
                                         uint32_t b0, uint32_t b1) {
    asm volatile(
        "mma.sync.aligned.m16n8k16.row.col.f32.bf16.bf16.f32 "
        "{%0,%1,%2,%3}, {%4,%5,%6,%7}, {%8,%9}, {%0,%1,%2,%3};"
        : "+f"(c[0]), "+f"(c[1]), "+f"(c[2]), "+f"(c[3])
        : "r"(a[0]), "r"(a[1]), "r"(a[2]), "r"(a[3]), "r"(b0), "r"(b1));
}

// smem tile layout: stride 136 halfs (272 B) -> ldmatrix conflict-free
#define TSTR      136
#define TILE_B    (128 * TSTR * 2)   // 34816 B
#define SM_AHI    0
#define SM_ALO    (SM_AHI + TILE_B)
#define SM_WHI    (SM_ALO + TILE_B)
#define SM_WLO    (SM_WHI + TILE_B)
#define SM_TOTAL  (SM_WLO + TILE_B)  // 139264 B

// ---------------------------------------------------------------------------
// GEMM via mma.sync bf16 (3-term split), fp32 in, fp16 out.
// CTA: 128 rows x 128 cols.  8 warps = 4(M) x 2(N), warp tile 32x64.
// ---------------------------------------------------------------------------
extern "C" __global__ void __launch_bounds__(256, 1)
gmm_gemm_mma(const float* __restrict__ A, const float* __restrict__ W,
             __half* __restrict__ C, int N)
{
    extern __shared__ char smem[];
    const uint32_t sbase = smem_u32(smem);
    const int tid  = threadIdx.x;
    const int lane = tid & 31;
    const int wid  = tid >> 5;
    const int rowBase = blockIdx.x * 128;

    // ---- stage W (hi/lo split) ----
    for (int idx = tid; idx < 4096; idx += 256) {       // 4096 float4s
        int row = idx >> 5;
        int k0  = (idx & 31) * 4;
        float4 v = *(const float4*)&W[(size_t)row * IN_F + k0];
        float hx = __bfloat162float(__float2bfloat16(v.x));
        float hy = __bfloat162float(__float2bfloat16(v.y));
        float hz = __bfloat162float(__float2bfloat16(v.z));
        float hw = __bfloat162float(__float2bfloat16(v.w));
        uint32_t off = (uint32_t)(row * TSTR + k0) * 2u;
        *(uint2*)(smem + SM_WHI + off) =
            make_uint2(pack_bf2(hx, hy), pack_bf2(hz, hw));
        *(uint2*)(smem + SM_WLO + off) =
            make_uint2(pack_bf2(v.x - hx, v.y - hy),
                       pack_bf2(v.z - hz, v.w - hw));
    }
    // ---- stage A tile (hi/lo split) ----
    for (int idx = tid; idx < 4096; idx += 256) {
        int row = idx >> 5;
        int k0  = (idx & 31) * 4;
        int gr  = rowBase + row;
        float4 v = make_float4(0.f, 0.f, 0.f, 0.f);
        if (gr < N) v = *(const float4*)&A[(size_t)gr * IN_F + k0];
        float hx = __bfloat162float(__float2bfloat16(v.x));
        float hy = __bfloat162float(__float2bfloat16(v.y));
        float hz = __bfloat162float(__float2bfloat16(v.z));
        float hw = __bfloat162float(__float2bfloat16(v.w));
        uint32_t off = (uint32_t)(row * TSTR + k0) * 2u;
        *(uint2*)(smem + SM_AHI + off) =
            make_uint2(pack_bf2(hx, hy), pack_bf2(hz, hw));
        *(uint2*)(smem + SM_ALO + off) =
            make_uint2(pack_bf2(v.x - hx, v.y - hy),
                       pack_bf2(v.z - hz, v.w - hw));
    }
    __syncthreads();

    const int warp_m = wid & 3;       // M 32-chunk
    const int warp_n = wid >> 2;      // N 64-chunk

    float acc[2][8][4];
#pragma unroll
    for (int r = 0; r < 2; r++)
#pragma unroll
        for (int j = 0; j < 8; j++)
#pragma unroll
            for (int c = 0; c < 4; c++) acc[r][j][c] = 0.0f;

    // per-lane ldmatrix address pieces
    const int a_row = warp_m * 32 + (lane & 15);
    const int a_kb  = (lane >> 4) * 8;
    const int b_mi  = lane >> 3;               // matrix idx 0..3
    const int b_n   = warp_n * 64 + (b_mi & 1) * 8 + (lane & 7);
    const int b_kb  = (b_mi >> 1) * 8;

#pragma unroll
    for (int kk = 0; kk < 8; kk++) {
        const int k0 = kk * 16;
        uint32_t ah[2][4], al[2][4];
#pragma unroll
        for (int r = 0; r < 2; r++) {
            uint32_t off = (uint32_t)((a_row + r * 16) * TSTR + k0 + a_kb) * 2u;
            ldsm4(ah[r], sbase + SM_AHI + off);
            ldsm4(al[r], sbase + SM_ALO + off);
        }
        uint32_t bh[4][4], bl[4][4];
#pragma unroll
        for (int nf2 = 0; nf2 < 4; nf2++) {
            uint32_t off =
                (uint32_t)((b_n + nf2 * 16) * TSTR + k0 + b_kb) * 2u;
            ldsm4(bh[nf2], sbase + SM_WHI + off);
            ldsm4(bl[nf2], sbase + SM_WLO + off);
        }
#pragma unroll
        for (int r = 0; r < 2; r++) {
#pragma unroll
            for (int nf2 = 0; nf2 < 4; nf2++) {
                // even n-frag: {m0,m2}; odd n-frag: {m1,m3}
                mma_bf16(acc[r][nf2 * 2 + 0], ah[r], bh[nf2][0], bh[nf2][2]);
                mma_bf16(acc[r][nf2 * 2 + 1], ah[r], bh[nf2][1], bh[nf2][3]);
                mma_bf16(acc[r][nf2 * 2 + 0], ah[r], bl[nf2][0], bl[nf2][2]);
                mma_bf16(acc[r][nf2 * 2 + 1], ah[r], bl[nf2][1], bl[nf2][3]);
                mma_bf16(acc[r][nf2 * 2 + 0], al[r], bh[nf2][0], bh[nf2][2]);
                mma_bf16(acc[r][nf2 * 2 + 1], al[r], bh[nf2][1], bh[nf2][3]);
            }
        }
    }

    // ---- epilogue: fp16 stores straight from accumulators ----
#pragma unroll
    for (int r = 0; r < 2; r++) {
        int gr0 = rowBase + warp_m * 32 + r * 16 + (lane >> 2);
#pragma unroll
        for (int j = 0; j < 8; j++) {
            int col = warp_n * 64 + j * 8 + (lane & 3) * 2;
            if (gr0 < N) {
                __half2 h = __floats2half2_rn(acc[r][j][0], acc[r][j][1]);
                *(__half2*)&C[(size_t)gr0 * KO + col] = h;
            }
            if (gr0 + 8 < N) {
                __half2 h = __floats2half2_rn(acc[r][j][2], acc[r][j][3]);
                *(__half2*)&C[(size_t)(gr0 + 8) * KO + col] = h;
            }
        }
    }
}

// ---------------------------------------------------------------------------
// Edge phase: one warp per dst node, fp16 NF gather (8B/lane).
// Stage 1: lanes 0-15 fetch metadata; 2 exps/lane -> smem weights.
// Stage 2: unrolled gather: LDS src + LDS w + LDG.64 + 4 FFMA.
// ---------------------------------------------------------------------------
extern "C" __global__ void __launch_bounds__(256, 4)
gmm_edge_kernel(const int* __restrict__ rowptr, const int* __restrict__ colind,
                const int* __restrict__ permute, const float* __restrict__ pseudo,
                const float* __restrict__ mu, const float* __restrict__ inv_sigma,
                const float* __restrict__ bias, const __half* __restrict__ NF,
                float* __restrict__ out, int N)
{
    __shared__ int    s_src[8][16];
    __shared__ float2 s_p[8][16];
    __shared__ float  s_w[8][64];    // [e*4 + k]

    const unsigned FULL = 0xffffffffu;
    const int lane  = threadIdx.x & 31;
    const int wrp   = threadIdx.x >> 5;
    const int gwarp = (blockIdx.x * blockDim.x + threadIdx.x) >> 5;
    const int nwarp = (gridDim.x * blockDim.x) >> 5;

    const int k  = lane >> 3;   // gaussian kernel 0..3
    const int f4 = lane & 7;    // half4 index within OUT_F

    const int kh = lane >> 4;
    const float muA0 = mu[4 * kh + 0], muA1 = mu[4 * kh + 1];
    const float muB0 = mu[4 * kh + 2], muB1 = mu[4 * kh + 3];
    const float isA0 = inv_sigma[4 * kh + 0], isA1 = inv_sigma[4 * kh + 1];
    const float isB0 = inv_sigma[4 * kh + 2], isB1 = inv_sigma[4 * kh + 3];

    float4 bv = make_float4(0.f, 0.f, 0.f, 0.f);
    if (lane < 8) bv = *(const float4*)&bias[f4 * 4];

    for (int i = gwarp; i < N; i += nwarp) {
        const int e0 = rowptr[i];
        const int e1 = rowptr[i + 1];

        float4 acc = make_float4(0.f, 0.f, 0.f, 0.f);

        for (int base = e0; base < e1; base += 16) {
            const int cnt = min(16, e1 - base);

            if (lane < cnt) {
                s_src[wrp][lane] = colind[base + lane];
                int pi = permute[base + lane];
                s_p[wrp][lane] = ((const float2*)pseudo)[pi];
            }
            __syncwarp(FULL);

            {
                int e = lane & 15;
                if (e < cnt) {
                    float2 p = s_p[wrp][e];
                    float d0 = (p.x - muA0) * isA0;
                    float d1 = (p.y - muA1) * isA1;
                    s_w[wrp][e * 4 + 2 * kh] =
                        __expf(-0.5f * (d0 * d0 + d1 * d1));
                    d0 = (p.x - muB0) * isB0;
                    d1 = (p.y - muB1) * isB1;
                    s_w[wrp][e * 4 + 2 * kh + 1] =
                        __expf(-0.5f * (d0 * d0 + d1 * d1));
                }
            }
            __syncwarp(FULL);

            if (cnt == 16) {
#pragma unroll
                for (int e = 0; e < 16; e++) {
                    int   src = s_src[wrp][e];
                    float w   = s_w[wrp][e * 4 + k];
                    uint2 raw = *(const uint2*)
                        (NF + (size_t)src * KO + k * OUT_F + f4 * 4);
                    float2 f0 = __half22float2(*reinterpret_cast<__half2*>(&raw.x));
                    float2 f1 = __half22float2(*reinterpret_cast<__half2*>(&raw.y));
                    acc.x += w * f0.x;
                    acc.y += w * f0.y;
                    acc.z += w * f1.x;
                    acc.w += w * f1.y;
                }
            } else {
                for (int e = 0; e < cnt; e++) {
                    int   src = s_src[wrp][e];
                    float w   = s_w[wrp][e * 4 + k];
                    uint2 raw = *(const uint2*)
                        (NF + (size_t)src * KO + k * OUT_F + f4 * 4);
                    float2 f0 = __half22float2(*reinterpret_cast<__half2*>(&raw.x));
                    float2 f1 = __half22float2(*reinterpret_cast<__half2*>(&raw.y));
                    acc.x += w * f0.x;
                    acc.y += w * f0.y;
                    acc.z += w * f1.x;
                    acc.w += w * f1.y;
                }
            }
            __syncwarp(FULL);
        }

        acc.x += __shfl_xor_sync(FULL, acc.x, 8);
        acc.y += __shfl_xor_sync(FULL, acc.y, 8);
        acc.z += __shfl_xor_sync(FULL, acc.z, 8);
        acc.w += __shfl_xor_sync(FULL, acc.w, 8);
        acc.x += __shfl_xor_sync(FULL, acc.x, 16);
        acc.y += __shfl_xor_sync(FULL, acc.y, 16);
        acc.z += __shfl_xor_sync(FULL, acc.z, 16);
        acc.w += __shfl_xor_sync(FULL, acc.w, 16);

        if (lane < 8) {
            float4 o;
            o.x = acc.x + bv.x;
            o.y = acc.y + bv.y;
            o.z = acc.z + bv.z;
            o.w = acc.w + bv.w;
            *(float4*)&out[(size_t)i * OUT_F + f4 * 4] = o;
        }
    }
}

// ---------------------------------------------------------------------------
// Inputs (metadata order):
//  0 rowptr[N+1] i32, 1 colind[E] i32, 2 colptr i32, 3 rowind i32,
//  4 permute[E] i32, 5 feat[N*128] f32, 6 pseudo[E*2] f32,
//  7 fc_w[128*128] f32, 8 mu[4*2] f32, 9 inv_sigma[4*2] f32, 10 bias[32] f32
// ---------------------------------------------------------------------------
extern "C" void kernel_launch(void* const* d_in, const int* in_sizes, int n_in,
                              void* d_out, int out_size)
{
    const int*   rowptr    = (const int*)  d_in[0];
    const int*   colind    = (const int*)  d_in[1];
    const int*   permute   = (const int*)  d_in[4];
    const float* feat      = (const float*)d_in[5];
    const float* pseudo    = (const float*)d_in[6];
    const float* fc_w      = (const float*)d_in[7];
    const float* mu        = (const float*)d_in[8];
    const float* inv_sigma = (const float*)d_in[9];
    const float* bias      = (const float*)d_in[10];

    const int N = in_sizes[5] / IN_F;

    __half* nf;
    cudaGetSymbolAddress((void**)&nf, g_nf);

    cudaFuncSetAttribute(gmm_gemm_mma,
                         cudaFuncAttributeMaxDynamicSharedMemorySize, SM_TOTAL);
    const int gemm_blocks = (N + 127) / 128;
    gmm_gemm_mma<<<gemm_blocks, 256, SM_TOTAL>>>(feat, fc_w, nf, N);

    const int edge_blocks = (N * 32 + 255) / 256;
    gmm_edge_kernel<<<edge_blocks, 256>>>(rowptr, colind, permute, pseudo,
                                          mu, inv_sigma, bias, nf,
                                          (float*)d_out, N);
}

// round 5
// speedup vs baseline: 1.8961x; 1.6196x over previous
#include <cuda_runtime.h>
#include <cuda_bf16.h>
#include <cuda_fp16.h>
#include <cstdint>

#define IN_F   128
#define KGAUSS 4
#define OUT_F  32
#define KO     128   // KGAUSS * OUT_F

// node_feat scratch: [N][K*OUT_F] fp16
__device__ __half g_nf[100096 * 128];

// ---------------------------------------------------------------------------
// helpers
// ---------------------------------------------------------------------------
__device__ __forceinline__ uint32_t smem_u32(const void* p) {
    uint32_t a;
    asm("{ .reg .u64 t; cvta.to.shared.u64 t, %1; cvt.u32.u64 %0, t; }"
        : "=r"(a) : "l"(p));
    return a;
}
__device__ __forceinline__ unsigned pack_h2f(float a, float b) {
    __half2 h = __floats2half2_rn(a, b);
    return *reinterpret_cast<unsigned*>(&h);
}
__device__ __forceinline__ void ldsm4(uint32_t r[4], uint32_t addr) {
    asm volatile(
        "ldmatrix.sync.aligned.m8n8.x4.shared.b16 {%0,%1,%2,%3}, [%4];"
        : "=r"(r[0]), "=r"(r[1]), "=r"(r[2]), "=r"(r[3]) : "r"(addr));
}
__device__ __forceinline__ void mma_f16(float c[4], const uint32_t a[4],
                                        uint32_t b0, uint32_t b1) {
    asm volatile(
        "mma.sync.aligned.m16n8k16.row.col.f32.f16.f16.f32 "
        "{%0,%1,%2,%3}, {%4,%5,%6,%7}, {%8,%9}, {%0,%1,%2,%3};"
        : "+f"(c[0]), "+f"(c[1]), "+f"(c[2]), "+f"(c[3])
        : "r"(a[0]), "r"(a[1]), "r"(a[2]), "r"(a[3]), "r"(b0), "r"(b1));
}

// smem tile layout: stride 136 halfs (272 B) -> ldmatrix conflict-free
#define TSTR      136
#define TILE_B    (128 * TSTR * 2)   // 34816 B
#define SM_A      0
#define SM_W      (SM_A + TILE_B)
#define SM_TOTAL  (SM_W + TILE_B)    // 69632 B -> 2 CTAs/SM

// ---------------------------------------------------------------------------
// GEMM via mma.sync fp16 (single-pass), fp32 in, fp16 out.
// CTA: 128 rows x 128 cols.  8 warps = 4(M) x 2(N), warp tile 32x64.
// ---------------------------------------------------------------------------
extern "C" __global__ void __launch_bounds__(256, 2)
gmm_gemm_mma(const float* __restrict__ A, const float* __restrict__ W,
             __half* __restrict__ C, int N)
{
    extern __shared__ char smem[];
    const uint32_t sbase = smem_u32(smem);
    const int tid  = threadIdx.x;
    const int lane = tid & 31;
    const int wid  = tid >> 5;
    const int rowBase = blockIdx.x * 128;

    // ---- stage A tile + W, converted to fp16 ----
    for (int idx = tid; idx < 4096; idx += 256) {       // 4096 float4s each
        int row = idx >> 5;
        int k0  = (idx & 31) * 4;
        uint32_t off = (uint32_t)(row * TSTR + k0) * 2u;

        float4 w = *(const float4*)&W[(size_t)row * IN_F + k0];
        *(uint2*)(smem + SM_W + off) =
            make_uint2(pack_h2f(w.x, w.y), pack_h2f(w.z, w.w));

        int gr = rowBase + row;
        float4 v = make_float4(0.f, 0.f, 0.f, 0.f);
        if (gr < N) v = *(const float4*)&A[(size_t)gr * IN_F + k0];
        *(uint2*)(smem + SM_A + off) =
            make_uint2(pack_h2f(v.x, v.y), pack_h2f(v.z, v.w));
    }
    __syncthreads();

    const int warp_m = wid & 3;       // M 32-chunk
    const int warp_n = wid >> 2;      // N 64-chunk

    float acc[2][8][4];
#pragma unroll
    for (int r = 0; r < 2; r++)
#pragma unroll
        for (int j = 0; j < 8; j++)
#pragma unroll
            for (int c = 0; c < 4; c++) acc[r][j][c] = 0.0f;

    // per-lane ldmatrix address pieces
    const int a_row = warp_m * 32 + (lane & 15);
    const int a_kb  = (lane >> 4) * 8;
    const int b_mi  = lane >> 3;               // matrix idx 0..3
    const int b_n   = warp_n * 64 + (b_mi & 1) * 8 + (lane & 7);
    const int b_kb  = (b_mi >> 1) * 8;

#pragma unroll
    for (int kk = 0; kk < 8; kk++) {
        const int k0 = kk * 16;
        uint32_t af[2][4];
#pragma unroll
        for (int r = 0; r < 2; r++) {
            uint32_t off = (uint32_t)((a_row + r * 16) * TSTR + k0 + a_kb) * 2u;
            ldsm4(af[r], sbase + SM_A + off);
        }
        uint32_t bf[4][4];
#pragma unroll
        for (int nf2 = 0; nf2 < 4; nf2++) {
            uint32_t off =
                (uint32_t)((b_n + nf2 * 16) * TSTR + k0 + b_kb) * 2u;
            ldsm4(bf[nf2], sbase + SM_W + off);
        }
#pragma unroll
        for (int r = 0; r < 2; r++) {
#pragma unroll
            for (int nf2 = 0; nf2 < 4; nf2++) {
                // even n-frag: {m0,m2}; odd n-frag: {m1,m3}
                mma_f16(acc[r][nf2 * 2 + 0], af[r], bf[nf2][0], bf[nf2][2]);
                mma_f16(acc[r][nf2 * 2 + 1], af[r], bf[nf2][1], bf[nf2][3]);
            }
        }
    }

    // ---- epilogue: fp16 stores straight from accumulators ----
#pragma unroll
    for (int r = 0; r < 2; r++) {
        int gr0 = rowBase + warp_m * 32 + r * 16 + (lane >> 2);
#pragma unroll
        for (int j = 0; j < 8; j++) {
            int col = warp_n * 64 + j * 8 + (lane & 3) * 2;
            if (gr0 < N) {
                __half2 h = __floats2half2_rn(acc[r][j][0], acc[r][j][1]);
                *(__half2*)&C[(size_t)gr0 * KO + col] = h;
            }
            if (gr0 + 8 < N) {
                __half2 h = __floats2half2_rn(acc[r][j][2], acc[r][j][3]);
                *(__half2*)&C[(size_t)(gr0 + 8) * KO + col] = h;
            }
        }
    }
}

// ---------------------------------------------------------------------------
// Edge phase: one warp per dst node, fp16 NF gather (8B/lane).
// Stage 1: lanes 0-15 fetch metadata; 2 exps/lane -> smem weights.
// Stage 2: unrolled gather: LDS src + LDS w + LDG.64 + 4 FFMA.
// ---------------------------------------------------------------------------
extern "C" __global__ void __launch_bounds__(256, 4)
gmm_edge_kernel(const int* __restrict__ rowptr, const int* __restrict__ colind,
                const int* __restrict__ permute, const float* __restrict__ pseudo,
                const float* __restrict__ mu, const float* __restrict__ inv_sigma,
                const float* __restrict__ bias, const __half* __restrict__ NF,
                float* __restrict__ out, int N)
{
    __shared__ int    s_src[8][16];
    __shared__ float2 s_p[8][16];
    __shared__ float  s_w[8][64];    // [e*4 + k]

    const unsigned FULL = 0xffffffffu;
    const int lane  = threadIdx.x & 31;
    const int wrp   = threadIdx.x >> 5;
    const int gwarp = (blockIdx.x * blockDim.x + threadIdx.x) >> 5;
    const int nwarp = (gridDim.x * blockDim.x) >> 5;

    const int k  = lane >> 3;   // gaussian kernel 0..3
    const int f4 = lane & 7;    // half4 index within OUT_F

    const int kh = lane >> 4;
    const float muA0 = mu[4 * kh + 0], muA1 = mu[4 * kh + 1];
    const float muB0 = mu[4 * kh + 2], muB1 = mu[4 * kh + 3];
    const float isA0 = inv_sigma[4 * kh + 0], isA1 = inv_sigma[4 * kh + 1];
    const float isB0 = inv_sigma[4 * kh + 2], isB1 = inv_sigma[4 * kh + 3];

    float4 bv = make_float4(0.f, 0.f, 0.f, 0.f);
    if (lane < 8) bv = *(const float4*)&bias[f4 * 4];

    for (int i = gwarp; i < N; i += nwarp) {
        const int e0 = rowptr[i];
        const int e1 = rowptr[i + 1];

        float4 acc = make_float4(0.f, 0.f, 0.f, 0.f);

        for (int base = e0; base < e1; base += 16) {
            const int cnt = min(16, e1 - base);

            if (lane < cnt) {
                s_src[wrp][lane] = colind[base + lane];
                int pi = permute[base + lane];
                s_p[wrp][lane] = ((const float2*)pseudo)[pi];
            }
            __syncwarp(FULL);

            {
                int e = lane & 15;
                if (e < cnt) {
                    float2 p = s_p[wrp][e];
                    float d0 = (p.x - muA0) * isA0;
                    float d1 = (p.y - muA1) * isA1;
                    s_w[wrp][e * 4 + 2 * kh] =
                        __expf(-0.5f * (d0 * d0 + d1 * d1));
                    d0 = (p.x - muB0) * isB0;
                    d1 = (p.y - muB1) * isB1;
                    s_w[wrp][e * 4 + 2 * kh + 1] =
                        __expf(-0.5f * (d0 * d0 + d1 * d1));
                }
            }
            __syncwarp(FULL);

            if (cnt == 16) {
#pragma unroll
                for (int e = 0; e < 16; e++) {
                    int   src = s_src[wrp][e];
                    float w   = s_w[wrp][e * 4 + k];
                    uint2 raw = *(const uint2*)
                        (NF + (size_t)src * KO + k * OUT_F + f4 * 4);
                    float2 f0 = __half22float2(*reinterpret_cast<__half2*>(&raw.x));
                    float2 f1 = __half22float2(*reinterpret_cast<__half2*>(&raw.y));
                    acc.x += w * f0.x;
                    acc.y += w * f0.y;
                    acc.z += w * f1.x;
                    acc.w += w * f1.y;
                }
            } else {
                for (int e = 0; e < cnt; e++) {
                    int   src = s_src[wrp][e];
                    float w   = s_w[wrp][e * 4 + k];
                    uint2 raw = *(const uint2*)
                        (NF + (size_t)src * KO + k * OUT_F + f4 * 4);
                    float2 f0 = __half22float2(*reinterpret_cast<__half2*>(&raw.x));
                    float2 f1 = __half22float2(*reinterpret_cast<__half2*>(&raw.y));
                    acc.x += w * f0.x;
                    acc.y += w * f0.y;
                    acc.z += w * f1.x;
                    acc.w += w * f1.y;
                }
            }
            __syncwarp(FULL);
        }

        acc.x += __shfl_xor_sync(FULL, acc.x, 8);
        acc.y += __shfl_xor_sync(FULL, acc.y, 8);
        acc.z += __shfl_xor_sync(FULL, acc.z, 8);
        acc.w += __shfl_xor_sync(FULL, acc.w, 8);
        acc.x += __shfl_xor_sync(FULL, acc.x, 16);
        acc.y += __shfl_xor_sync(FULL, acc.y, 16);
        acc.z += __shfl_xor_sync(FULL, acc.z, 16);
        acc.w += __shfl_xor_sync(FULL, acc.w, 16);

        if (lane < 8) {
            float4 o;
            o.x = acc.x + bv.x;
            o.y = acc.y + bv.y;
            o.z = acc.z + bv.z;
            o.w = acc.w + bv.w;
            *(float4*)&out[(size_t)i * OUT_F + f4 * 4] = o;
        }
    }
}

// ---------------------------------------------------------------------------
// Inputs (metadata order):
//  0 rowptr[N+1] i32, 1 colind[E] i32, 2 colptr i32, 3 rowind i32,
//  4 permute[E] i32, 5 feat[N*128] f32, 6 pseudo[E*2] f32,
//  7 fc_w[128*128] f32, 8 mu[4*2] f32, 9 inv_sigma[4*2] f32, 10 bias[32] f32
// ---------------------------------------------------------------------------
extern "C" void kernel_launch(void* const* d_in, const int* in_sizes, int n_in,
                              void* d_out, int out_size)
{
    const int*   rowptr    = (const int*)  d_in[0];
    const int*   colind    = (const int*)  d_in[1];
    const int*   permute   = (const int*)  d_in[4];
    const float* feat      = (const float*)d_in[5];
    const float* pseudo    = (const float*)d_in[6];
    const float* fc_w      = (const float*)d_in[7];
    const float* mu        = (const float*)d_in[8];
    const float* inv_sigma = (const float*)d_in[9];
    const float* bias      = (const float*)d_in[10];

    const int N = in_sizes[5] / IN_F;

    __half* nf;
    cudaGetSymbolAddress((void**)&nf, g_nf);

    cudaFuncSetAttribute(gmm_gemm_mma,
                         cudaFuncAttributeMaxDynamicSharedMemorySize, SM_TOTAL);
    const int gemm_blocks = (N + 127) / 128;
    gmm_gemm_mma<<<gemm_blocks, 256, SM_TOTAL>>>(feat, fc_w, nf, N);

    const int edge_blocks = (N * 32 + 255) / 256;
    gmm_edge_kernel<<<edge_blocks, 256>>>(rowptr, colind, permute, pseudo,
                                          mu, inv_sigma, bias, nf,
                                          (float*)d_out, N);
}

// round 6
// speedup vs baseline: 2.5560x; 1.3480x over previous
#include <cuda_runtime.h>
#include <cuda_bf16.h>
#include <cuda_fp16.h>
#include <cstdint>

#define IN_F   128
#define KGAUSS 4
#define OUT_F  32
#define KO     128   // KGAUSS * OUT_F

// node_feat scratch: [N][K*OUT_F] fp16
__device__ __half g_nf[100096 * 128];

// ---------------------------------------------------------------------------
// helpers
// ---------------------------------------------------------------------------
__device__ __forceinline__ uint32_t smem_u32(const void* p) {
    uint32_t a;
    asm("{ .reg .u64 t; cvta.to.shared.u64 t, %1; cvt.u32.u64 %0, t; }"
        : "=r"(a) : "l"(p));
    return a;
}
__device__ __forceinline__ unsigned pack_h2f(float a, float b) {
    __half2 h = __floats2half2_rn(a, b);
    return *reinterpret_cast<unsigned*>(&h);
}
__device__ __forceinline__ void ldsm4(uint32_t r[4], uint32_t addr) {
    asm volatile(
        "ldmatrix.sync.aligned.m8n8.x4.shared.b16 {%0,%1,%2,%3}, [%4];"
        : "=r"(r[0]), "=r"(r[1]), "=r"(r[2]), "=r"(r[3]) : "r"(addr));
}
__device__ __forceinline__ void mma_f16(float c[4], const uint32_t a[4],
                                        uint32_t b0, uint32_t b1) {
    asm volatile(
        "mma.sync.aligned.m16n8k16.row.col.f32.f16.f16.f32 "
        "{%0,%1,%2,%3}, {%4,%5,%6,%7}, {%8,%9}, {%0,%1,%2,%3};"
        : "+f"(c[0]), "+f"(c[1]), "+f"(c[2]), "+f"(c[3])
        : "r"(a[0]), "r"(a[1]), "r"(a[2]), "r"(a[3]), "r"(b0), "r"(b1));
}

// smem tile layout: stride 136 halfs (272 B) -> ldmatrix conflict-free
#define TSTR      136
#define TILE_B    (128 * TSTR * 2)   // 34816 B
#define SM_A      0
#define SM_W      (SM_A + TILE_B)
#define SM_TOTAL  (SM_W + TILE_B)    // 69632 B -> 2 CTAs/SM

// ---------------------------------------------------------------------------
// GEMM via mma.sync fp16 (single-pass), fp32 in, fp16 out.
// CTA: 128 rows x 128 cols.  8 warps = 4(M) x 2(N), warp tile 32x64.
// ---------------------------------------------------------------------------
extern "C" __global__ void __launch_bounds__(256, 2)
gmm_gemm_mma(const float* __restrict__ A, const float* __restrict__ W,
             __half* __restrict__ C, int N)
{
    extern __shared__ char smem[];
    const uint32_t sbase = smem_u32(smem);
    const int tid  = threadIdx.x;
    const int lane = tid & 31;
    const int wid  = tid >> 5;
    const int rowBase = blockIdx.x * 128;

    // ---- stage A tile + W, converted to fp16 (fully unrolled for MLP) ----
#pragma unroll
    for (int it = 0; it < 16; it++) {
        int idx = tid + it * 256;
        int row = idx >> 5;
        int k0  = (idx & 31) * 4;
        uint32_t off = (uint32_t)(row * TSTR + k0) * 2u;

        float4 w = *(const float4*)&W[(size_t)row * IN_F + k0];
        int gr = rowBase + row;
        float4 v = make_float4(0.f, 0.f, 0.f, 0.f);
        if (gr < N) v = *(const float4*)&A[(size_t)gr * IN_F + k0];

        *(uint2*)(smem + SM_W + off) =
            make_uint2(pack_h2f(w.x, w.y), pack_h2f(w.z, w.w));
        *(uint2*)(smem + SM_A + off) =
            make_uint2(pack_h2f(v.x, v.y), pack_h2f(v.z, v.w));
    }
    __syncthreads();

    const int warp_m = wid & 3;       // M 32-chunk
    const int warp_n = wid >> 2;      // N 64-chunk

    float acc[2][8][4];
#pragma unroll
    for (int r = 0; r < 2; r++)
#pragma unroll
        for (int j = 0; j < 8; j++)
#pragma unroll
            for (int c = 0; c < 4; c++) acc[r][j][c] = 0.0f;

    // per-lane ldmatrix address pieces
    const int a_row = warp_m * 32 + (lane & 15);
    const int a_kb  = (lane >> 4) * 8;
    const int b_mi  = lane >> 3;               // matrix idx 0..3
    const int b_n   = warp_n * 64 + (b_mi & 1) * 8 + (lane & 7);
    const int b_kb  = (b_mi >> 1) * 8;

#pragma unroll
    for (int kk = 0; kk < 8; kk++) {
        const int k0 = kk * 16;
        uint32_t af[2][4];
#pragma unroll
        for (int r = 0; r < 2; r++) {
            uint32_t off = (uint32_t)((a_row + r * 16) * TSTR + k0 + a_kb) * 2u;
            ldsm4(af[r], sbase + SM_A + off);
        }
        uint32_t bf[4][4];
#pragma unroll
        for (int nf2 = 0; nf2 < 4; nf2++) {
            uint32_t off =
                (uint32_t)((b_n + nf2 * 16) * TSTR + k0 + b_kb) * 2u;
            ldsm4(bf[nf2], sbase + SM_W + off);
        }
#pragma unroll
        for (int r = 0; r < 2; r++) {
#pragma unroll
            for (int nf2 = 0; nf2 < 4; nf2++) {
                // even n-frag: {m0,m2}; odd n-frag: {m1,m3}
                mma_f16(acc[r][nf2 * 2 + 0], af[r], bf[nf2][0], bf[nf2][2]);
                mma_f16(acc[r][nf2 * 2 + 1], af[r], bf[nf2][1], bf[nf2][3]);
            }
        }
    }

    // ---- epilogue: fp16 stores straight from accumulators ----
#pragma unroll
    for (int r = 0; r < 2; r++) {
        int gr0 = rowBase + warp_m * 32 + r * 16 + (lane >> 2);
#pragma unroll
        for (int j = 0; j < 8; j++) {
            int col = warp_n * 64 + j * 8 + (lane & 3) * 2;
            if (gr0 < N) {
                __half2 h = __floats2half2_rn(acc[r][j][0], acc[r][j][1]);
                *(__half2*)&C[(size_t)gr0 * KO + col] = h;
            }
            if (gr0 + 8 < N) {
                __half2 h = __floats2half2_rn(acc[r][j][2], acc[r][j][3]);
                *(__half2*)&C[(size_t)(gr0 + 8) * KO + col] = h;
            }
        }
    }
}

// ---------------------------------------------------------------------------
// Edge phase: PERSISTENT grid, one warp per dst node per iteration.
// Stage 1: lanes 0-15 fetch metadata; 2 exps/lane -> smem weights.
// Stage 2: unrolled gather: LDS src + LDS w + LDG.64 + 4 FFMA.
// ---------------------------------------------------------------------------
#define EDGE_BLOCKS 592   // ~4 CTAs/SM on 148 SMs

extern "C" __global__ void __launch_bounds__(256, 4)
gmm_edge_kernel(const int* __restrict__ rowptr, const int* __restrict__ colind,
                const int* __restrict__ permute, const float* __restrict__ pseudo,
                const float* __restrict__ mu, const float* __restrict__ inv_sigma,
                const float* __restrict__ bias, const __half* __restrict__ NF,
                float* __restrict__ out, int N)
{
    __shared__ int    s_src[8][16];
    __shared__ float2 s_p[8][16];
    __shared__ float  s_w[8][64];    // [e*4 + k]

    const unsigned FULL = 0xffffffffu;
    const int lane  = threadIdx.x & 31;
    const int wrp   = threadIdx.x >> 5;
    const int gwarp = (blockIdx.x * blockDim.x + threadIdx.x) >> 5;
    const int nwarp = (gridDim.x * blockDim.x) >> 5;

    const int k  = lane >> 3;   // gaussian kernel 0..3
    const int f4 = lane & 7;    // half4 index within OUT_F

    const int kh = lane >> 4;
    const float muA0 = mu[4 * kh + 0], muA1 = mu[4 * kh + 1];
    const float muB0 = mu[4 * kh + 2], muB1 = mu[4 * kh + 3];
    const float isA0 = inv_sigma[4 * kh + 0], isA1 = inv_sigma[4 * kh + 1];
    const float isB0 = inv_sigma[4 * kh + 2], isB1 = inv_sigma[4 * kh + 3];

    float4 bv = make_float4(0.f, 0.f, 0.f, 0.f);
    if (lane < 8) bv = *(const float4*)&bias[f4 * 4];

    // lane-constant slice of NF rows
    const __half* NF_lane = NF + k * OUT_F + f4 * 4;

    for (int i = gwarp; i < N; i += nwarp) {
        const int e0 = rowptr[i];
        const int e1 = rowptr[i + 1];

        float4 acc = make_float4(0.f, 0.f, 0.f, 0.f);

        for (int base = e0; base < e1; base += 16) {
            const int cnt = min(16, e1 - base);

            if (lane < cnt) {
                s_src[wrp][lane] = colind[base + lane];
                int pi = permute[base + lane];
                s_p[wrp][lane] = ((const float2*)pseudo)[pi];
            }
            __syncwarp(FULL);

            {
                int e = lane & 15;
                if (e < cnt) {
                    float2 p = s_p[wrp][e];
                    float d0 = (p.x - muA0) * isA0;
                    float d1 = (p.y - muA1) * isA1;
                    s_w[wrp][e * 4 + 2 * kh] =
                        __expf(-0.5f * (d0 * d0 + d1 * d1));
                    d0 = (p.x - muB0) * isB0;
                    d1 = (p.y - muB1) * isB1;
                    s_w[wrp][e * 4 + 2 * kh + 1] =
                        __expf(-0.5f * (d0 * d0 + d1 * d1));
                }
            }
            __syncwarp(FULL);

            if (cnt == 16) {
#pragma unroll
                for (int e = 0; e < 16; e++) {
                    int   src = s_src[wrp][e];
                    float w   = s_w[wrp][e * 4 + k];
                    uint2 raw = *(const uint2*)(NF_lane + (size_t)src * KO);
                    float2 f0 = __half22float2(*reinterpret_cast<__half2*>(&raw.x));
                    float2 f1 = __half22float2(*reinterpret_cast<__half2*>(&raw.y));
                    acc.x += w * f0.x;
                    acc.y += w * f0.y;
                    acc.z += w * f1.x;
                    acc.w += w * f1.y;
                }
            } else {
                for (int e = 0; e < cnt; e++) {
                    int   src = s_src[wrp][e];
                    float w   = s_w[wrp][e * 4 + k];
                    uint2 raw = *(const uint2*)(NF_lane + (size_t)src * KO);
                    float2 f0 = __half22float2(*reinterpret_cast<__half2*>(&raw.x));
                    float2 f1 = __half22float2(*reinterpret_cast<__half2*>(&raw.y));
                    acc.x += w * f0.x;
                    acc.y += w * f0.y;
                    acc.z += w * f1.x;
                    acc.w += w * f1.y;
                }
            }
            __syncwarp(FULL);
        }

        acc.x += __shfl_xor_sync(FULL, acc.x, 8);
        acc.y += __shfl_xor_sync(FULL, acc.y, 8);
        acc.z += __shfl_xor_sync(FULL, acc.z, 8);
        acc.w += __shfl_xor_sync(FULL, acc.w, 8);
        acc.x += __shfl_xor_sync(FULL, acc.x, 16);
        acc.y += __shfl_xor_sync(FULL, acc.y, 16);
        acc.z += __shfl_xor_sync(FULL, acc.z, 16);
        acc.w += __shfl_xor_sync(FULL, acc.w, 16);

        if (lane < 8) {
            float4 o;
            o.x = acc.x + bv.x;
            o.y = acc.y + bv.y;
            o.z = acc.z + bv.z;
            o.w = acc.w + bv.w;
            *(float4*)&out[(size_t)i * OUT_F + f4 * 4] = o;
        }
    }
}

// ---------------------------------------------------------------------------
// Inputs (metadata order):
//  0 rowptr[N+1] i32, 1 colind[E] i32, 2 colptr i32, 3 rowind i32,
//  4 permute[E] i32, 5 feat[N*128] f32, 6 pseudo[E*2] f32,
//  7 fc_w[128*128] f32, 8 mu[4*2] f32, 9 inv_sigma[4*2] f32, 10 bias[32] f32
// ---------------------------------------------------------------------------
extern "C" void kernel_launch(void* const* d_in, const int* in_sizes, int n_in,
                              void* d_out, int out_size)
{
    const int*   rowptr    = (const int*)  d_in[0];
    const int*   colind    = (const int*)  d_in[1];
    const int*   permute   = (const int*)  d_in[4];
    const float* feat      = (const float*)d_in[5];
    const float* pseudo    = (const float*)d_in[6];
    const float* fc_w      = (const float*)d_in[7];
    const float* mu        = (const float*)d_in[8];
    const float* inv_sigma = (const float*)d_in[9];
    const float* bias      = (const float*)d_in[10];

    const int N = in_sizes[5] / IN_F;

    __half* nf;
    cudaGetSymbolAddress((void**)&nf, g_nf);

    cudaFuncSetAttribute(gmm_gemm_mma,
                         cudaFuncAttributeMaxDynamicSharedMemorySize, SM_TOTAL);
    const int gemm_blocks = (N + 127) / 128;
    gmm_gemm_mma<<<gemm_blocks, 256, SM_TOTAL>>>(feat, fc_w, nf, N);

    gmm_edge_kernel<<<EDGE_BLOCKS, 256>>>(rowptr, colind, permute, pseudo,
                                          mu, inv_sigma, bias, nf,
                                          (float*)d_out, N);
}

// round 7
// speedup vs baseline: 2.7823x; 1.0885x over previous
#include <cuda_runtime.h>
#include <cuda_bf16.h>
#include <cuda_fp16.h>
#include <cstdint>

#define IN_F   128
#define KGAUSS 4
#define OUT_F  32
#define KO     128   // KGAUSS * OUT_F

// node_feat scratch: [N][K*OUT_F] fp16
__device__ __half g_nf[100096 * 128];

// ---------------------------------------------------------------------------
// helpers
// ---------------------------------------------------------------------------
__device__ __forceinline__ uint32_t smem_u32(const void* p) {
    uint32_t a;
    asm("{ .reg .u64 t; cvta.to.shared.u64 t, %1; cvt.u32.u64 %0, t; }"
        : "=r"(a) : "l"(p));
    return a;
}
__device__ __forceinline__ unsigned pack_h2f(float a, float b) {
    __half2 h = __floats2half2_rn(a, b);
    return *reinterpret_cast<unsigned*>(&h);
}
__device__ __forceinline__ void ldsm4(uint32_t r[4], uint32_t addr) {
    asm volatile(
        "ldmatrix.sync.aligned.m8n8.x4.shared.b16 {%0,%1,%2,%3}, [%4];"
        : "=r"(r[0]), "=r"(r[1]), "=r"(r[2]), "=r"(r[3]) : "r"(addr));
}
__device__ __forceinline__ void mma_f16(float c[4], const uint32_t a[4],
                                        uint32_t b0, uint32_t b1) {
    asm volatile(
        "mma.sync.aligned.m16n8k16.row.col.f32.f16.f16.f32 "
        "{%0,%1,%2,%3}, {%4,%5,%6,%7}, {%8,%9}, {%0,%1,%2,%3};"
        : "+f"(c[0]), "+f"(c[1]), "+f"(c[2]), "+f"(c[3])
        : "r"(a[0]), "r"(a[1]), "r"(a[2]), "r"(a[3]), "r"(b0), "r"(b1));
}

// smem tile layout: stride 136 halfs (272 B) -> ldmatrix conflict-free
#define TSTR      136
#define TILE_B    (128 * TSTR * 2)   // 34816 B
#define SM_A      0
#define SM_W      (SM_A + TILE_B)
#define SM_TOTAL  (SM_W + TILE_B)    // 69632 B -> 2 CTAs/SM

// ---------------------------------------------------------------------------
// GEMM via mma.sync fp16 (single-pass), fp32 in, fp16 out.
// CTA: 128 rows x 128 cols.  8 warps = 4(M) x 2(N), warp tile 32x64.
// ---------------------------------------------------------------------------
extern "C" __global__ void __launch_bounds__(256, 2)
gmm_gemm_mma(const float* __restrict__ A, const float* __restrict__ W,
             __half* __restrict__ C, int N)
{
    extern __shared__ char smem[];
    const uint32_t sbase = smem_u32(smem);
    const int tid  = threadIdx.x;
    const int lane = tid & 31;
    const int wid  = tid >> 5;
    const int rowBase = blockIdx.x * 128;

#pragma unroll
    for (int it = 0; it < 16; it++) {
        int idx = tid + it * 256;
        int row = idx >> 5;
        int k0  = (idx & 31) * 4;
        uint32_t off = (uint32_t)(row * TSTR + k0) * 2u;

        float4 w = *(const float4*)&W[(size_t)row * IN_F + k0];
        int gr = rowBase + row;
        float4 v = make_float4(0.f, 0.f, 0.f, 0.f);
        if (gr < N) v = *(const float4*)&A[(size_t)gr * IN_F + k0];

        *(uint2*)(smem + SM_W + off) =
            make_uint2(pack_h2f(w.x, w.y), pack_h2f(w.z, w.w));
        *(uint2*)(smem + SM_A + off) =
            make_uint2(pack_h2f(v.x, v.y), pack_h2f(v.z, v.w));
    }
    __syncthreads();

    const int warp_m = wid & 3;
    const int warp_n = wid >> 2;

    float acc[2][8][4];
#pragma unroll
    for (int r = 0; r < 2; r++)
#pragma unroll
        for (int j = 0; j < 8; j++)
#pragma unroll
            for (int c = 0; c < 4; c++) acc[r][j][c] = 0.0f;

    const int a_row = warp_m * 32 + (lane & 15);
    const int a_kb  = (lane >> 4) * 8;
    const int b_mi  = lane >> 3;
    const int b_n   = warp_n * 64 + (b_mi & 1) * 8 + (lane & 7);
    const int b_kb  = (b_mi >> 1) * 8;

#pragma unroll
    for (int kk = 0; kk < 8; kk++) {
        const int k0 = kk * 16;
        uint32_t af[2][4];
#pragma unroll
        for (int r = 0; r < 2; r++) {
            uint32_t off = (uint32_t)((a_row + r * 16) * TSTR + k0 + a_kb) * 2u;
            ldsm4(af[r], sbase + SM_A + off);
        }
        uint32_t bf[4][4];
#pragma unroll
        for (int nf2 = 0; nf2 < 4; nf2++) {
            uint32_t off =
                (uint32_t)((b_n + nf2 * 16) * TSTR + k0 + b_kb) * 2u;
            ldsm4(bf[nf2], sbase + SM_W + off);
        }
#pragma unroll
        for (int r = 0; r < 2; r++) {
#pragma unroll
            for (int nf2 = 0; nf2 < 4; nf2++) {
                mma_f16(acc[r][nf2 * 2 + 0], af[r], bf[nf2][0], bf[nf2][2]);
                mma_f16(acc[r][nf2 * 2 + 1], af[r], bf[nf2][1], bf[nf2][3]);
            }
        }
    }

#pragma unroll
    for (int r = 0; r < 2; r++) {
        int gr0 = rowBase + warp_m * 32 + r * 16 + (lane >> 2);
#pragma unroll
        for (int j = 0; j < 8; j++) {
            int col = warp_n * 64 + j * 8 + (lane & 3) * 2;
            if (gr0 < N) {
                __half2 h = __floats2half2_rn(acc[r][j][0], acc[r][j][1]);
                *(__half2*)&C[(size_t)gr0 * KO + col] = h;
            }
            if (gr0 + 8 < N) {
                __half2 h = __floats2half2_rn(acc[r][j][2], acc[r][j][3]);
                *(__half2*)&C[(size_t)(gr0 + 8) * KO + col] = h;
            }
        }
    }
}

// ---------------------------------------------------------------------------
// Edge phase v3: persistent grid, ONE WARP = TWO NODES (16 lanes each).
//   Pack stage: lane hl owns edge hl of its node; computes all 4 gaussian
//               weights, stores (src, w) pairs to smem.
//   Gather:     lane hl covers (k = hl>>2, f = 8*(hl&3)); per edge one
//               LDS.64 (src+w) + one LDG.128 (16B of the NF row) + 8 FFMA.
//   Reduce:     shfl_xor 4, 8 sums over k; lanes hl<4 write 32B each.
// ---------------------------------------------------------------------------
#define EDGE_BLOCKS 592   // 4 CTAs/SM on 148 SMs, one wave

extern "C" __global__ void __launch_bounds__(256, 4)
gmm_edge_kernel(const int* __restrict__ rowptr, const int* __restrict__ colind,
                const int* __restrict__ permute, const float* __restrict__ pseudo,
                const float* __restrict__ mu, const float* __restrict__ inv_sigma,
                const float* __restrict__ bias, const __half* __restrict__ NF,
                float* __restrict__ out, int N)
{
    __shared__ uint2 s_pack[8][2][16][4];   // [warp][half][edge][k] = (src, w)

    const unsigned FULL = 0xffffffffu;
    const int lane  = threadIdx.x & 31;
    const int wrp   = threadIdx.x >> 5;
    const int hn    = lane >> 4;        // which node of the pair
    const int hl    = lane & 15;        // lane within half
    const int gwarp = (blockIdx.x * blockDim.x + threadIdx.x) >> 5;
    const int nwarp = (gridDim.x * blockDim.x) >> 5;

    const int kq = hl >> 2;             // k this lane gathers
    // gaussian params (all 4 kernels) in registers
    float2 muk[4], isk[4];
#pragma unroll
    for (int k = 0; k < 4; k++) {
        muk[k] = ((const float2*)mu)[k];
        isk[k] = ((const float2*)inv_sigma)[k];
    }
    float4 b0 = make_float4(0.f, 0.f, 0.f, 0.f);
    float4 b1 = make_float4(0.f, 0.f, 0.f, 0.f);
    if (hl < 4) {
        b0 = *(const float4*)&bias[hl * 8];
        b1 = *(const float4*)&bias[hl * 8 + 4];
    }

    const int npairs = (N + 1) >> 1;

    for (int p = gwarp; p < npairs; p += nwarp) {
        const int node  = 2 * p + hn;
        const bool valid = node < N;
        int e0 = 0, e1 = 0;
        if (valid) { e0 = rowptr[node]; e1 = rowptr[node + 1]; }

        float acc[8];
#pragma unroll
        for (int j = 0; j < 8; j++) acc[j] = 0.0f;

        int base = e0;
        while (__any_sync(FULL, base < e1)) {
            int cnt = e1 - base;
            cnt = cnt < 0 ? 0 : (cnt > 16 ? 16 : cnt);

            // ---- pack stage: one edge per lane, all 4 weights ----
            if (hl < cnt) {
                int ei  = base + hl;
                int src = colind[ei];
                int pi  = permute[ei];
                float2 pp = ((const float2*)pseudo)[pi];
#pragma unroll
                for (int k = 0; k < 4; k++) {
                    float d0 = (pp.x - muk[k].x) * isk[k].x;
                    float d1 = (pp.y - muk[k].y) * isk[k].y;
                    float w  = __expf(-0.5f * (d0 * d0 + d1 * d1));
                    s_pack[wrp][hn][hl][k] =
                        make_uint2((unsigned)src, __float_as_uint(w));
                }
            }
            __syncwarp(FULL);

            // ---- gather stage ----
            if (cnt == 16) {
#pragma unroll
                for (int e = 0; e < 16; e++) {
                    uint2 pk = s_pack[wrp][hn][e][kq];
                    float w  = __uint_as_float(pk.y);
                    const uint4* vp =
                        (const uint4*)(NF + (size_t)pk.x * KO);
                    uint4 v = vp[hl];
                    float2 f0 = __half22float2(*reinterpret_cast<__half2*>(&v.x));
                    float2 f1 = __half22float2(*reinterpret_cast<__half2*>(&v.y));
                    float2 f2 = __half22float2(*reinterpret_cast<__half2*>(&v.z));
                    float2 f3 = __half22float2(*reinterpret_cast<__half2*>(&v.w));
                    acc[0] += w * f0.x;  acc[1] += w * f0.y;
                    acc[2] += w * f1.x;  acc[3] += w * f1.y;
                    acc[4] += w * f2.x;  acc[5] += w * f2.y;
                    acc[6] += w * f3.x;  acc[7] += w * f3.y;
                }
            } else {
                for (int e = 0; e < cnt; e++) {
                    uint2 pk = s_pack[wrp][hn][e][kq];
                    float w  = __uint_as_float(pk.y);
                    const uint4* vp =
                        (const uint4*)(NF + (size_t)pk.x * KO);
                    uint4 v = vp[hl];
                    float2 f0 = __half22float2(*reinterpret_cast<__half2*>(&v.x));
                    float2 f1 = __half22float2(*reinterpret_cast<__half2*>(&v.y));
                    float2 f2 = __half22float2(*reinterpret_cast<__half2*>(&v.z));
                    float2 f3 = __half22float2(*reinterpret_cast<__half2*>(&v.w));
                    acc[0] += w * f0.x;  acc[1] += w * f0.y;
                    acc[2] += w * f1.x;  acc[3] += w * f1.y;
                    acc[4] += w * f2.x;  acc[5] += w * f2.y;
                    acc[6] += w * f3.x;  acc[7] += w * f3.y;
                }
            }
            __syncwarp(FULL);
            base += 16;
        }

        // ---- reduce over k (lane bits 2,3 of hl) ----
#pragma unroll
        for (int j = 0; j < 8; j++) {
            acc[j] += __shfl_xor_sync(FULL, acc[j], 4);
            acc[j] += __shfl_xor_sync(FULL, acc[j], 8);
        }

        if (hl < 4 && valid) {
            float* dst = out + (size_t)node * OUT_F + hl * 8;
            float4 o0 = make_float4(acc[0] + b0.x, acc[1] + b0.y,
                                    acc[2] + b0.z, acc[3] + b0.w);
            float4 o1 = make_float4(acc[4] + b1.x, acc[5] + b1.y,
                                    acc[6] + b1.z, acc[7] + b1.w);
            *(float4*)dst       = o0;
            *(float4*)(dst + 4) = o1;
        }
    }
}

// ---------------------------------------------------------------------------
// Inputs (metadata order):
//  0 rowptr[N+1] i32, 1 colind[E] i32, 2 colptr i32, 3 rowind i32,
//  4 permute[E] i32, 5 feat[N*128] f32, 6 pseudo[E*2] f32,
//  7 fc_w[128*128] f32, 8 mu[4*2] f32, 9 inv_sigma[4*2] f32, 10 bias[32] f32
// ---------------------------------------------------------------------------
extern "C" void kernel_launch(void* const* d_in, const int* in_sizes, int n_in,
                              void* d_out, int out_size)
{
    const int*   rowptr    = (const int*)  d_in[0];
    const int*   colind    = (const int*)  d_in[1];
    const int*   permute   = (const int*)  d_in[4];
    const float* feat      = (const float*)d_in[5];
    const float* pseudo    = (const float*)d_in[6];
    const float* fc_w      = (const float*)d_in[7];
    const float* mu        = (const float*)d_in[8];
    const float* inv_sigma = (const float*)d_in[9];
    const float* bias      = (const float*)d_in[10];

    const int N = in_sizes[5] / IN_F;

    __half* nf;
    cudaGetSymbolAddress((void**)&nf, g_nf);

    cudaFuncSetAttribute(gmm_gemm_mma,
                         cudaFuncAttributeMaxDynamicSharedMemorySize, SM_TOTAL);
    const int gemm_blocks = (N + 127) / 128;
    gmm_gemm_mma<<<gemm_blocks, 256, SM_TOTAL>>>(feat, fc_w, nf, N);

    gmm_edge_kernel<<<EDGE_BLOCKS, 256>>>(rowptr, colind, permute, pseudo,
                                          mu, inv_sigma, bias, nf,
                                          (float*)d_out, N);
}

// round 8
// speedup vs baseline: 3.0359x; 1.0911x over previous
#include <cuda_runtime.h>
#include <cuda_bf16.h>
#include <cuda_fp16.h>
#include <cstdint>

#define IN_F   128
#define KGAUSS 4
#define OUT_F  32
#define KO     128   // KGAUSS * OUT_F

// node_feat scratch: [N][K*OUT_F] fp16
__device__ __half g_nf[100096 * 128];

// ---------------------------------------------------------------------------
// helpers
// ---------------------------------------------------------------------------
__device__ __forceinline__ uint32_t smem_u32(const void* p) {
    uint32_t a;
    asm("{ .reg .u64 t; cvta.to.shared.u64 t, %1; cvt.u32.u64 %0, t; }"
        : "=r"(a) : "l"(p));
    return a;
}
__device__ __forceinline__ unsigned pack_h2f(float a, float b) {
    __half2 h = __floats2half2_rn(a, b);
    return *reinterpret_cast<unsigned*>(&h);
}
__device__ __forceinline__ void ldsm4(uint32_t r[4], uint32_t addr) {
    asm volatile(
        "ldmatrix.sync.aligned.m8n8.x4.shared.b16 {%0,%1,%2,%3}, [%4];"
        : "=r"(r[0]), "=r"(r[1]), "=r"(r[2]), "=r"(r[3]) : "r"(addr));
}
__device__ __forceinline__ void mma_f16(float c[4], const uint32_t a[4],
                                        uint32_t b0, uint32_t b1) {
    asm volatile(
        "mma.sync.aligned.m16n8k16.row.col.f32.f16.f16.f32 "
        "{%0,%1,%2,%3}, {%4,%5,%6,%7}, {%8,%9}, {%0,%1,%2,%3};"
        : "+f"(c[0]), "+f"(c[1]), "+f"(c[2]), "+f"(c[3])
        : "r"(a[0]), "r"(a[1]), "r"(a[2]), "r"(a[3]), "r"(b0), "r"(b1));
}

// smem tile layout: stride 136 halfs (272 B) -> ldmatrix conflict-free
#define TSTR      136
#define TILE_B    (128 * TSTR * 2)   // 34816 B
#define SM_A      0
#define SM_W      (SM_A + TILE_B)
#define SM_TOTAL  (SM_W + TILE_B)    // 69632 B -> 2 CTAs/SM

// ---------------------------------------------------------------------------
// GEMM via mma.sync fp16 (single-pass), fp32 in, fp16 out.
// ---------------------------------------------------------------------------
extern "C" __global__ void __launch_bounds__(256, 2)
gmm_gemm_mma(const float* __restrict__ A, const float* __restrict__ W,
             __half* __restrict__ C, int N)
{
    extern __shared__ char smem[];
    const uint32_t sbase = smem_u32(smem);
    const int tid  = threadIdx.x;
    const int lane = tid & 31;
    const int wid  = tid >> 5;
    const int rowBase = blockIdx.x * 128;

#pragma unroll
    for (int it = 0; it < 16; it++) {
        int idx = tid + it * 256;
        int row = idx >> 5;
        int k0  = (idx & 31) * 4;
        uint32_t off = (uint32_t)(row * TSTR + k0) * 2u;

        float4 w = *(const float4*)&W[(size_t)row * IN_F + k0];
        int gr = rowBase + row;
        float4 v = make_float4(0.f, 0.f, 0.f, 0.f);
        if (gr < N) v = *(const float4*)&A[(size_t)gr * IN_F + k0];

        *(uint2*)(smem + SM_W + off) =
            make_uint2(pack_h2f(w.x, w.y), pack_h2f(w.z, w.w));
        *(uint2*)(smem + SM_A + off) =
            make_uint2(pack_h2f(v.x, v.y), pack_h2f(v.z, v.w));
    }
    __syncthreads();

    const int warp_m = wid & 3;
    const int warp_n = wid >> 2;

    float acc[2][8][4];
#pragma unroll
    for (int r = 0; r < 2; r++)
#pragma unroll
        for (int j = 0; j < 8; j++)
#pragma unroll
            for (int c = 0; c < 4; c++) acc[r][j][c] = 0.0f;

    const int a_row = warp_m * 32 + (lane & 15);
    const int a_kb  = (lane >> 4) * 8;
    const int b_mi  = lane >> 3;
    const int b_n   = warp_n * 64 + (b_mi & 1) * 8 + (lane & 7);
    const int b_kb  = (b_mi >> 1) * 8;

#pragma unroll
    for (int kk = 0; kk < 8; kk++) {
        const int k0 = kk * 16;
        uint32_t af[2][4];
#pragma unroll
        for (int r = 0; r < 2; r++) {
            uint32_t off = (uint32_t)((a_row + r * 16) * TSTR + k0 + a_kb) * 2u;
            ldsm4(af[r], sbase + SM_A + off);
        }
        uint32_t bf[4][4];
#pragma unroll
        for (int nf2 = 0; nf2 < 4; nf2++) {
            uint32_t off =
                (uint32_t)((b_n + nf2 * 16) * TSTR + k0 + b_kb) * 2u;
            ldsm4(bf[nf2], sbase + SM_W + off);
        }
#pragma unroll
        for (int r = 0; r < 2; r++) {
#pragma unroll
            for (int nf2 = 0; nf2 < 4; nf2++) {
                mma_f16(acc[r][nf2 * 2 + 0], af[r], bf[nf2][0], bf[nf2][2]);
                mma_f16(acc[r][nf2 * 2 + 1], af[r], bf[nf2][1], bf[nf2][3]);
            }
        }
    }

#pragma unroll
    for (int r = 0; r < 2; r++) {
        int gr0 = rowBase + warp_m * 32 + r * 16 + (lane >> 2);
#pragma unroll
        for (int j = 0; j < 8; j++) {
            int col = warp_n * 64 + j * 8 + (lane & 3) * 2;
            if (gr0 < N) {
                __half2 h = __floats2half2_rn(acc[r][j][0], acc[r][j][1]);
                *(__half2*)&C[(size_t)gr0 * KO + col] = h;
            }
            if (gr0 + 8 < N) {
                __half2 h = __floats2half2_rn(acc[r][j][2], acc[r][j][3]);
                *(__half2*)&C[(size_t)(gr0 + 8) * KO + col] = h;
            }
        }
    }
}

// ---------------------------------------------------------------------------
// Edge phase v4: persistent grid, one warp = two nodes, DEPTH-2 SOFTWARE
// PIPELINE on metadata: while gathering pair p, pseudo for p+1 and
// rowptr/colind/permute for p+2 are in flight.
// ---------------------------------------------------------------------------
#define EDGE_BLOCKS 592   // 4 CTAs/SM on 148 SMs, one wave

extern "C" __global__ void __launch_bounds__(256, 4)
gmm_edge_kernel(const int* __restrict__ rowptr, const int* __restrict__ colind,
                const int* __restrict__ permute, const float* __restrict__ pseudo,
                const float* __restrict__ mu, const float* __restrict__ inv_sigma,
                const float* __restrict__ bias, const __half* __restrict__ NF,
                float* __restrict__ out, int N)
{
    __shared__ uint2  s_pack[8][2][16][4];   // [warp][half][edge][k] = (src, w)
    __shared__ float4 s_gp[4];               // (mu.x, mu.y, is.x, is.y) per k

    const unsigned FULL = 0xffffffffu;
    const int lane  = threadIdx.x & 31;
    const int wrp   = threadIdx.x >> 5;
    const int hn    = lane >> 4;        // which node of the pair
    const int hl    = lane & 15;        // lane within half
    const int gwarp = (blockIdx.x * blockDim.x + threadIdx.x) >> 5;
    const int nwarp = (gridDim.x * blockDim.x) >> 5;
    const int kq    = hl >> 2;          // k this lane gathers

    if (threadIdx.x < 4) {
        s_gp[threadIdx.x] = make_float4(mu[2 * threadIdx.x],
                                        mu[2 * threadIdx.x + 1],
                                        inv_sigma[2 * threadIdx.x],
                                        inv_sigma[2 * threadIdx.x + 1]);
    }
    __syncthreads();

    float4 b0 = make_float4(0.f, 0.f, 0.f, 0.f);
    float4 b1 = make_float4(0.f, 0.f, 0.f, 0.f);
    if (hl < 4) {
        b0 = *(const float4*)&bias[hl * 8];
        b1 = *(const float4*)&bias[hl * 8 + 4];
    }

    const float2* pseudo2 = (const float2*)pseudo;
    const int npairs = (N + 1) >> 1;

    // metadata loader for pair pp (per-lane edge hl of node hn)
    auto load_meta = [&](int pp, int& e0o, int& dego, int& srco, int& pio) {
        e0o = 0; dego = 0; srco = 0; pio = 0;
        int nd = 2 * pp + hn;
        if (pp < npairs && nd < N) {
            int a = rowptr[nd];
            int b = rowptr[nd + 1];
            e0o = a;
            dego = b - a;
            int cap = dego < 16 ? dego : 16;
            if (hl < cap) {
                srco = colind[a + hl];
                pio  = permute[a + hl];
            }
        }
    };

    // ---- pipeline prologue ----
    int p = gwarp;
    int e0_c, deg_c, src_c, pi_c;
    int e0_n, deg_n, src_n, pi_n;
    float2 pp_c = make_float2(0.f, 0.f);
    load_meta(p, e0_c, deg_c, src_c, pi_c);
    if (hl < (deg_c < 16 ? deg_c : 16)) pp_c = pseudo2[pi_c];
    load_meta(p + nwarp, e0_n, deg_n, src_n, pi_n);

    for (; p < npairs; p += nwarp) {
        const int node  = 2 * p + hn;
        const bool valid = node < N;
        const int cnt = deg_c < 16 ? deg_c : 16;

        // ---- pack current pair's weights ----
        if (hl < cnt) {
#pragma unroll
            for (int k = 0; k < 4; k++) {
                float4 g = s_gp[k];
                float d0 = (pp_c.x - g.x) * g.z;
                float d1 = (pp_c.y - g.y) * g.w;
                float w  = __expf(-0.5f * (d0 * d0 + d1 * d1));
                s_pack[wrp][hn][hl][k] =
                    make_uint2((unsigned)src_c, __float_as_uint(w));
            }
        }

        // ---- prefetch: pseudo for p+1, meta for p+2 ----
        float2 pp_n = make_float2(0.f, 0.f);
        if (hl < (deg_n < 16 ? deg_n : 16)) pp_n = pseudo2[pi_n];
        int e0_2, deg_2, src_2, pi_2;
        load_meta(p + 2 * nwarp, e0_2, deg_2, src_2, pi_2);

        __syncwarp(FULL);

        // ---- gather current pair ----
        float acc[8];
#pragma unroll
        for (int j = 0; j < 8; j++) acc[j] = 0.0f;

        if (cnt == 16) {
#pragma unroll
            for (int e = 0; e < 16; e++) {
                uint2 pk = s_pack[wrp][hn][e][kq];
                float w  = __uint_as_float(pk.y);
                uint4 v  = ((const uint4*)(NF + (size_t)pk.x * KO))[hl];
                float2 f0 = __half22float2(*reinterpret_cast<__half2*>(&v.x));
                float2 f1 = __half22float2(*reinterpret_cast<__half2*>(&v.y));
                float2 f2 = __half22float2(*reinterpret_cast<__half2*>(&v.z));
                float2 f3 = __half22float2(*reinterpret_cast<__half2*>(&v.w));
                acc[0] += w * f0.x;  acc[1] += w * f0.y;
                acc[2] += w * f1.x;  acc[3] += w * f1.y;
                acc[4] += w * f2.x;  acc[5] += w * f2.y;
                acc[6] += w * f3.x;  acc[7] += w * f3.y;
            }
        } else {
            for (int e = 0; e < cnt; e++) {
                uint2 pk = s_pack[wrp][hn][e][kq];
                float w  = __uint_as_float(pk.y);
                uint4 v  = ((const uint4*)(NF + (size_t)pk.x * KO))[hl];
                float2 f0 = __half22float2(*reinterpret_cast<__half2*>(&v.x));
                float2 f1 = __half22float2(*reinterpret_cast<__half2*>(&v.y));
                float2 f2 = __half22float2(*reinterpret_cast<__half2*>(&v.z));
                float2 f3 = __half22float2(*reinterpret_cast<__half2*>(&v.w));
                acc[0] += w * f0.x;  acc[1] += w * f0.y;
                acc[2] += w * f1.x;  acc[3] += w * f1.y;
                acc[4] += w * f2.x;  acc[5] += w * f2.y;
                acc[6] += w * f3.x;  acc[7] += w * f3.y;
            }
        }

        // ---- rare fallback: degree > 16 (not pipelined) ----
        if (__any_sync(FULL, deg_c > 16)) {
            float4 gq = s_gp[kq];
            for (int e = e0_c + 16; e < e0_c + deg_c; e++) {
                int src = colind[e];
                int pi  = permute[e];
                float2 pp = pseudo2[pi];
                float d0 = (pp.x - gq.x) * gq.z;
                float d1 = (pp.y - gq.y) * gq.w;
                float w  = __expf(-0.5f * (d0 * d0 + d1 * d1));
                uint4 v  = ((const uint4*)(NF + (size_t)src * KO))[hl];
                float2 f0 = __half22float2(*reinterpret_cast<__half2*>(&v.x));
                float2 f1 = __half22float2(*reinterpret_cast<__half2*>(&v.y));
                float2 f2 = __half22float2(*reinterpret_cast<__half2*>(&v.z));
                float2 f3 = __half22float2(*reinterpret_cast<__half2*>(&v.w));
                acc[0] += w * f0.x;  acc[1] += w * f0.y;
                acc[2] += w * f1.x;  acc[3] += w * f1.y;
                acc[4] += w * f2.x;  acc[5] += w * f2.y;
                acc[6] += w * f3.x;  acc[7] += w * f3.y;
            }
        }

        // ---- reduce over k (lane bits 2,3 of hl) ----
#pragma unroll
        for (int j = 0; j < 8; j++) {
            acc[j] += __shfl_xor_sync(FULL, acc[j], 4);
            acc[j] += __shfl_xor_sync(FULL, acc[j], 8);
        }

        if (hl < 4 && valid) {
            float* dst = out + (size_t)node * OUT_F + hl * 8;
            *(float4*)dst = make_float4(acc[0] + b0.x, acc[1] + b0.y,
                                        acc[2] + b0.z, acc[3] + b0.w);
            *(float4*)(dst + 4) = make_float4(acc[4] + b1.x, acc[5] + b1.y,
                                              acc[6] + b1.z, acc[7] + b1.w);
        }

        __syncwarp(FULL);   // protect s_pack before next pack overwrites

        // ---- rotate pipeline ----
        e0_c = e0_n; deg_c = deg_n; src_c = src_n; pp_c = pp_n;
        e0_n = e0_2; deg_n = deg_2; src_n = src_2; pi_n = pi_2;
    }
}

// ---------------------------------------------------------------------------
// Inputs (metadata order):
//  0 rowptr[N+1] i32, 1 colind[E] i32, 2 colptr i32, 3 rowind i32,
//  4 permute[E] i32, 5 feat[N*128] f32, 6 pseudo[E*2] f32,
//  7 fc_w[128*128] f32, 8 mu[4*2] f32, 9 inv_sigma[4*2] f32, 10 bias[32] f32
// ---------------------------------------------------------------------------
extern "C" void kernel_launch(void* const* d_in, const int* in_sizes, int n_in,
                              void* d_out, int out_size)
{
    const int*   rowptr    = (const int*)  d_in[0];
    const int*   colind    = (const int*)  d_in[1];
    const int*   permute   = (const int*)  d_in[4];
    const float* feat      = (const float*)d_in[5];
    const float* pseudo    = (const float*)d_in[6];
    const float* fc_w      = (const float*)d_in[7];
    const float* mu        = (const float*)d_in[8];
    const float* inv_sigma = (const float*)d_in[9];
    const float* bias      = (const float*)d_in[10];

    const int N = in_sizes[5] / IN_F;

    __half* nf;
    cudaGetSymbolAddress((void**)&nf, g_nf);

    cudaFuncSetAttribute(gmm_gemm_mma,
                         cudaFuncAttributeMaxDynamicSharedMemorySize, SM_TOTAL);
    const int gemm_blocks = (N + 127) / 128;
    gmm_gemm_mma<<<gemm_blocks, 256, SM_TOTAL>>>(feat, fc_w, nf, N);

    gmm_edge_kernel<<<EDGE_BLOCKS, 256>>>(rowptr, colind, permute, pseudo,
                                          mu, inv_sigma, bias, nf,
                                          (float*)d_out, N);
}